// round 1
// baseline (speedup 1.0000x reference)
#include <cuda_runtime.h>

// ---------------------------------------------------------------------------
// SpectralMSA: channel attention.
//   qkv = x @ Wqkv^T                      [B*N, 3C]
//   attn[b,h,d,e] = sum_n k[b,n,h,d]*q[b,n,h,e] / alpha[h]; softmax over e
//   out_tok[b,n,h*64+d] = sum_e P[b,h,d,e] * v[b,n,h,e]
//   y = out_tok @ Wproj^T + bproj
// All fp32. Round 1: tiled SGEMM baseline (FMA pipe), deterministic split-N
// partial sums for attention logits (no atomics -> bit-stable graph replays).
// ---------------------------------------------------------------------------

namespace {
constexpr int kB = 4;
constexpr int kN = 4096;
constexpr int kC = 1024;
constexpr int kH = 16;
constexpr int kD = 64;
constexpr int kM = kB * kN;        // 16384 tokens total
constexpr int kQKV = 3 * kC;       // 3072
constexpr int kSplits = 8;         // N-splits for attention logits
}

// Scratch (device globals: no allocation allowed in kernel_launch)
__device__ float g_qkv[(size_t)kM * kQKV];                       // 201 MB
__device__ float g_attn[(size_t)kSplits * kB * kH * kD * kD];    // 8 MB partials
__device__ float g_attnP[(size_t)kB * kH * kD * kD];             // 1 MB softmaxed
__device__ float g_out[(size_t)kM * kC];                         // 67 MB

// ---------------------------------------------------------------------------
// SGEMM (NT): C[m,n] = sum_k A[m,k] * B[n,k]  (+ optional bias[n])
// A: [M,K] row-major, B: [N,K] row-major. Tiles: 128x128x16, 256 thr, 8x8/thr.
// ---------------------------------------------------------------------------
template <bool HAS_BIAS>
__global__ __launch_bounds__(256, 2)
void sgemm_nt(const float* __restrict__ A, const float* __restrict__ B,
              float* __restrict__ C, const float* __restrict__ bias,
              int M, int N, int K)
{
    __shared__ float As[16][132];   // [k][m], padded (132*4B = 16B aligned)
    __shared__ float Bs[16][132];   // [k][n]

    const int t  = threadIdx.x;
    const int m0 = blockIdx.y * 128;
    const int n0 = blockIdx.x * 128;
    const int tm = t >> 4;          // 0..15 -> 8 m-rows
    const int tn = t & 15;          // 0..15 -> 8 n-cols

    const float* Ag = A + (size_t)m0 * K;
    const float* Bg = B + (size_t)n0 * K;

    float acc[8][8];
#pragma unroll
    for (int i = 0; i < 8; ++i)
#pragma unroll
        for (int j = 0; j < 8; ++j) acc[i][j] = 0.f;

    for (int k0 = 0; k0 < K; k0 += 16) {
#pragma unroll
        for (int i = 0; i < 2; ++i) {
            const int f = t + i * 256;          // 0..511
            const int row = f >> 2;             // 0..127
            const int c4 = (f & 3) * 4;         // 0,4,8,12
            float4 va = *(const float4*)(Ag + (size_t)row * K + k0 + c4);
            As[c4 + 0][row] = va.x; As[c4 + 1][row] = va.y;
            As[c4 + 2][row] = va.z; As[c4 + 3][row] = va.w;
            float4 vb = *(const float4*)(Bg + (size_t)row * K + k0 + c4);
            Bs[c4 + 0][row] = vb.x; Bs[c4 + 1][row] = vb.y;
            Bs[c4 + 2][row] = vb.z; Bs[c4 + 3][row] = vb.w;
        }
        __syncthreads();
#pragma unroll
        for (int kk = 0; kk < 16; ++kk) {
            float a[8], b[8];
            *(float4*)(a)     = *(const float4*)&As[kk][tm * 8];
            *(float4*)(a + 4) = *(const float4*)&As[kk][tm * 8 + 4];
            *(float4*)(b)     = *(const float4*)&Bs[kk][tn * 8];
            *(float4*)(b + 4) = *(const float4*)&Bs[kk][tn * 8 + 4];
#pragma unroll
            for (int i = 0; i < 8; ++i)
#pragma unroll
                for (int j = 0; j < 8; ++j)
                    acc[i][j] = fmaf(a[i], b[j], acc[i][j]);
        }
        __syncthreads();
    }

#pragma unroll
    for (int i = 0; i < 8; ++i) {
        const int m = m0 + tm * 8 + i;
        float* crow = C + (size_t)m * N + n0 + tn * 8;
#pragma unroll
        for (int j = 0; j < 8; j += 4) {
            float4 v = make_float4(acc[i][j], acc[i][j + 1],
                                   acc[i][j + 2], acc[i][j + 3]);
            if (HAS_BIAS) {
                const float* bp = bias + n0 + tn * 8 + j;
                v.x += bp[0]; v.y += bp[1]; v.z += bp[2]; v.w += bp[3];
            }
            *(float4*)(crow + j) = v;
        }
    }
}

// ---------------------------------------------------------------------------
// Attention logits, split over N: partial[s][bh][d][e] = sum_{n in split s}
// k[b,n,h,d] * q[b,n,h,e].  Deterministic (no atomics).
// Grid: (kSplits, B*H), 256 threads, each thread a 4x4 tile of the 64x64 out.
// ---------------------------------------------------------------------------
__global__ __launch_bounds__(256)
void attn_logits_kernel()
{
    __shared__ float Ks[64][68];
    __shared__ float Qs[64][68];

    const int t = threadIdx.x;
    const int split = blockIdx.x;        // 0..7
    const int bh = blockIdx.y;           // 0..63
    const int b = bh >> 4, h = bh & 15;

    const float* base = g_qkv + (size_t)b * kN * kQKV + h * kD;  // q offset
    const int td = t >> 4;               // 0..15 -> d rows (x4)
    const int te = t & 15;               // 0..15 -> e cols (x4)

    float acc[4][4];
#pragma unroll
    for (int i = 0; i < 4; ++i)
#pragma unroll
        for (int j = 0; j < 4; ++j) acc[i][j] = 0.f;

    const int nbeg = split * (kN / kSplits);
    for (int n0 = nbeg; n0 < nbeg + kN / kSplits; n0 += 64) {
#pragma unroll
        for (int i = 0; i < 4; ++i) {
            const int f = t + i * 256;       // 0..1023
            const int row = f >> 4;          // 0..63
            const int c4 = (f & 15) * 4;     // 0..60
            const float* p = base + (size_t)(n0 + row) * kQKV + c4;
            *(float4*)&Qs[row][c4] = *(const float4*)(p);        // q
            *(float4*)&Ks[row][c4] = *(const float4*)(p + kC);   // k
        }
        __syncthreads();
#pragma unroll
        for (int nn = 0; nn < 64; ++nn) {
            float a[4], q[4];
            *(float4*)a = *(const float4*)&Ks[nn][td * 4];
            *(float4*)q = *(const float4*)&Qs[nn][te * 4];
#pragma unroll
            for (int i = 0; i < 4; ++i)
#pragma unroll
                for (int j = 0; j < 4; ++j)
                    acc[i][j] = fmaf(a[i], q[j], acc[i][j]);
        }
        __syncthreads();
    }

    float* o = g_attn + ((size_t)split * (kB * kH) + bh) * (kD * kD);
#pragma unroll
    for (int i = 0; i < 4; ++i)
#pragma unroll
        for (int j = 0; j < 4; ++j)
            o[(td * 4 + i) * kD + te * 4 + j] = acc[i][j];
}

// ---------------------------------------------------------------------------
// Softmax over e (64), after summing split partials and dividing by alpha[h].
// Grid: B*H*D blocks of 64 threads.
// ---------------------------------------------------------------------------
__global__ void softmax_kernel(const float* __restrict__ alpha)
{
    const int row = blockIdx.x;          // 0..4095 = (b*16+h)*64 + d
    const int t = threadIdx.x;           // 0..63
    const int h = (row >> 6) & 15;
    __shared__ float s[64];

    float v = 0.f;
#pragma unroll
    for (int sp = 0; sp < kSplits; ++sp)
        v += g_attn[(size_t)sp * (kB * kH * kD * kD) + (size_t)row * kD + t];
    v /= alpha[h];

    s[t] = v;
    __syncthreads();
    for (int off = 32; off > 0; off >>= 1) {
        if (t < off) s[t] = fmaxf(s[t], s[t + off]);
        __syncthreads();
    }
    const float mx = s[0];
    __syncthreads();
    const float e = expf(v - mx);
    s[t] = e;
    __syncthreads();
    for (int off = 32; off > 0; off >>= 1) {
        if (t < off) s[t] += s[t + off];
        __syncthreads();
    }
    g_attnP[(size_t)row * kD + t] = e / s[0];
}

// ---------------------------------------------------------------------------
// P @ V^T: out_tok[b,n,h*64+d] = sum_e P[b,h,d,e] * v[b,n,h,e]
// Grid: (N/64, B*H), 256 threads; tile of 64 tokens x 64 d per block.
// ---------------------------------------------------------------------------
__global__ __launch_bounds__(256)
void pv_kernel()
{
    __shared__ float PsT[64][68];   // [e][d]
    __shared__ float Vs[64][68];    // [n_local][e]

    const int t = threadIdx.x;
    const int nt = blockIdx.x;      // 0..63 (64-token tiles)
    const int bh = blockIdx.y;      // 0..63
    const int b = bh >> 4, h = bh & 15;

    const float* Pg = g_attnP + (size_t)bh * (kD * kD);
#pragma unroll
    for (int i = 0; i < 4; ++i) {
        const int f = t + i * 256;
        const int dd = f >> 4;
        const int c4 = (f & 15) * 4;
        float4 v = *(const float4*)(Pg + dd * kD + c4);
        PsT[c4 + 0][dd] = v.x; PsT[c4 + 1][dd] = v.y;
        PsT[c4 + 2][dd] = v.z; PsT[c4 + 3][dd] = v.w;
    }
    const float* Vg = g_qkv + ((size_t)b * kN + nt * 64) * kQKV + 2 * kC + h * kD;
#pragma unroll
    for (int i = 0; i < 4; ++i) {
        const int f = t + i * 256;
        const int row = f >> 4;
        const int c4 = (f & 15) * 4;
        *(float4*)&Vs[row][c4] = *(const float4*)(Vg + (size_t)row * kQKV + c4);
    }
    __syncthreads();

    const int tn = t >> 3;          // 0..31 -> 2 token rows each
    const int tc = (t & 7) * 8;     // 0..56 -> 8 d cols

    float acc[2][8];
#pragma unroll
    for (int i = 0; i < 2; ++i)
#pragma unroll
        for (int j = 0; j < 8; ++j) acc[i][j] = 0.f;

#pragma unroll
    for (int e = 0; e < 64; ++e) {
        float p[8];
        *(float4*)(p)     = *(const float4*)&PsT[e][tc];
        *(float4*)(p + 4) = *(const float4*)&PsT[e][tc + 4];
#pragma unroll
        for (int i = 0; i < 2; ++i) {
            const float v = Vs[tn * 2 + i][e];
#pragma unroll
            for (int j = 0; j < 8; ++j)
                acc[i][j] = fmaf(v, p[j], acc[i][j]);
        }
    }

#pragma unroll
    for (int i = 0; i < 2; ++i) {
        const size_t n = (size_t)b * kN + nt * 64 + tn * 2 + i;
        float* dst = g_out + n * kC + h * kD + tc;
        *(float4*)(dst)     = make_float4(acc[i][0], acc[i][1], acc[i][2], acc[i][3]);
        *(float4*)(dst + 4) = make_float4(acc[i][4], acc[i][5], acc[i][6], acc[i][7]);
    }
}

// ---------------------------------------------------------------------------
extern "C" void kernel_launch(void* const* d_in, const int* in_sizes, int n_in,
                              void* d_out, int out_size)
{
    // Resolve inputs by element count (robust to metadata ordering).
    const float* x = nullptr;
    const float* Wqkv = nullptr;
    const float* Wproj = nullptr;
    const float* bproj = nullptr;
    const float* alpha = nullptr;
    for (int i = 0; i < n_in; ++i) {
        switch (in_sizes[i]) {
            case kM * kC:    x     = (const float*)d_in[i]; break; // 16777216
            case kQKV * kC:  Wqkv  = (const float*)d_in[i]; break; // 3145728
            case kC * kC:    Wproj = (const float*)d_in[i]; break; // 1048576
            case kC:         bproj = (const float*)d_in[i]; break; // 1024
            case kH:         alpha = (const float*)d_in[i]; break; // 16
            default: break;                                        // H, W (=1)
        }
    }

    float* qkv = nullptr;
    float* outp = nullptr;
    cudaGetSymbolAddress((void**)&qkv, g_qkv);
    cudaGetSymbolAddress((void**)&outp, g_out);

    // 1) QKV projection: [16384,1024] @ [3072,1024]^T -> [16384,3072]
    dim3 g1(kQKV / 128, kM / 128);
    sgemm_nt<false><<<g1, 256>>>(x, Wqkv, qkv, nullptr, kM, kQKV, kC);

    // 2) Channel-attention logits (split-N deterministic partials)
    attn_logits_kernel<<<dim3(kSplits, kB * kH), 256>>>();

    // 3) Softmax (+ alpha scaling, + partial reduction)
    softmax_kernel<<<kB * kH * kD, kD>>>(alpha);

    // 4) P @ V^T -> token-major out
    pv_kernel<<<dim3(kN / 64, kB * kH), 256>>>();

    // 5) Output projection + bias: [16384,1024] @ [1024,1024]^T -> d_out
    dim3 g3(kC / 128, kM / 128);
    sgemm_nt<true><<<g3, 256>>>(outp, Wproj, (float*)d_out, bproj, kM, kC, kC);
}

// round 3
// speedup vs baseline: 1.5606x; 1.5606x over previous
#include <cuda_runtime.h>
#include <cuda_bf16.h>

// ---------------------------------------------------------------------------
// SpectralMSA channel attention — Round 3: error-compensated bf16 GEMMs.
//   qkv = x @ Wqkv^T ; attn = softmax(k^T q / alpha) ; out = P @ v
//   y = out @ Wproj^T + bproj
// GEMM1/GEMM3: mma.sync m16n8k16 bf16, split-2 operands (hi+lo), 3 products
//   acc += aH*bH + aH*bL + aL*bH   (fp32 accumulate)  -> ~1e-5 rel precision.
// Attention path stays fp32 FMA (small fraction of time).
// ---------------------------------------------------------------------------

namespace {
constexpr int kB = 4;
constexpr int kN = 4096;
constexpr int kC = 1024;
constexpr int kH = 16;
constexpr int kD = 64;
constexpr int kM = kB * kN;        // 16384
constexpr int kQKV = 3 * kC;       // 3072
constexpr int kSplits = 8;
}

__device__ float g_qkv[(size_t)kM * kQKV];
__device__ float g_attn[(size_t)kSplits * kB * kH * kD * kD];
__device__ float g_attnP[(size_t)kB * kH * kD * kD];
__device__ float g_out[(size_t)kM * kC];

__device__ __forceinline__ void mma_bf16(float& d0, float& d1, float& d2, float& d3,
                                         unsigned a0, unsigned a1, unsigned a2, unsigned a3,
                                         unsigned b0, unsigned b1)
{
    asm volatile(
        "mma.sync.aligned.m16n8k16.row.col.f32.bf16.bf16.f32 "
        "{%0,%1,%2,%3},{%4,%5,%6,%7},{%8,%9},{%0,%1,%2,%3};"
        : "+f"(d0), "+f"(d1), "+f"(d2), "+f"(d3)
        : "r"(a0), "r"(a1), "r"(a2), "r"(a3), "r"(b0), "r"(b1));
}

// Split float4 (4 consecutive k) into two packed bf16x2 hi-words + lo-words.
__device__ __forceinline__ void split4(float4 v, unsigned& h0, unsigned& h1,
                                       unsigned& l0, unsigned& l1)
{
    __nv_bfloat16 ax = __float2bfloat16_rn(v.x);
    __nv_bfloat16 ay = __float2bfloat16_rn(v.y);
    __nv_bfloat16 az = __float2bfloat16_rn(v.z);
    __nv_bfloat16 aw = __float2bfloat16_rn(v.w);
    __nv_bfloat16 rx = __float2bfloat16_rn(v.x - __bfloat162float(ax));
    __nv_bfloat16 ry = __float2bfloat16_rn(v.y - __bfloat162float(ay));
    __nv_bfloat16 rz = __float2bfloat16_rn(v.z - __bfloat162float(az));
    __nv_bfloat16 rw = __float2bfloat16_rn(v.w - __bfloat162float(aw));
    __nv_bfloat162 p;
    p = __nv_bfloat162(ax, ay); h0 = *(unsigned*)&p;
    p = __nv_bfloat162(az, aw); h1 = *(unsigned*)&p;
    p = __nv_bfloat162(rx, ry); l0 = *(unsigned*)&p;
    p = __nv_bfloat162(rz, rw); l1 = *(unsigned*)&p;
}

// ---------------------------------------------------------------------------
// bf16x3 GEMM (NT): C[m,n] = sum_k A[m,k]*B[n,k] (+bias[n])
// Block 128x128x16, 256 thr. Warp grid 2(m) x 4(n); warp tile 64x32.
// smem planes [kpair][row] (uint32 = bf16x2), stride 136 -> conflict-free.
// One m16n8k16 k-step per 16-wide buffer; 3 mma (HH, HL, LH) per tile pair.
// ---------------------------------------------------------------------------
template <bool HAS_BIAS>
__global__ __launch_bounds__(256)
void bf16x3_gemm_nt(const float* __restrict__ A, const float* __restrict__ B,
                    float* __restrict__ C, const float* __restrict__ bias,
                    int M, int N, int K)
{
    __shared__ unsigned AsH[8][136], AsL[8][136];
    __shared__ unsigned BsH[8][136], BsL[8][136];

    const int t = threadIdx.x;
    const int warp = t >> 5, lane = t & 31;
    const int wm = (warp & 1) * 64;
    const int wn = (warp >> 1) * 32;
    const int r = lane >> 2, c = lane & 3;
    const int m0 = blockIdx.y * 128, n0 = blockIdx.x * 128;

    const int lrow = t & 127;
    const int lc0  = (t >> 7) * 4;       // k-cols lc0..lc0+3 and lc0+8..lc0+11
    const int kp0  = lc0 >> 1;           // kpair indices kp0, kp0+1 (and +4)

    const float* Ag = A + (size_t)(m0 + lrow) * K + lc0;
    const float* Bg = B + (size_t)(n0 + lrow) * K + lc0;

    float acc[4][4][4];
#pragma unroll
    for (int i = 0; i < 4; ++i)
#pragma unroll
        for (int j = 0; j < 4; ++j)
#pragma unroll
            for (int q = 0; q < 4; ++q) acc[i][j][q] = 0.f;

    float4 pa[2], pb[2];
#pragma unroll
    for (int i = 0; i < 2; ++i) {
        pa[i] = *(const float4*)(Ag + 8 * i);
        pb[i] = *(const float4*)(Bg + 8 * i);
    }

    for (int k0 = 0; k0 < K; k0 += 16) {
        // stage prefetched tile to smem as split bf16
#pragma unroll
        for (int i = 0; i < 2; ++i) {
            unsigned h0, h1, l0, l1;
            split4(pa[i], h0, h1, l0, l1);
            AsH[kp0 + 4 * i][lrow] = h0;  AsH[kp0 + 4 * i + 1][lrow] = h1;
            AsL[kp0 + 4 * i][lrow] = l0;  AsL[kp0 + 4 * i + 1][lrow] = l1;
            split4(pb[i], h0, h1, l0, l1);
            BsH[kp0 + 4 * i][lrow] = h0;  BsH[kp0 + 4 * i + 1][lrow] = h1;
            BsL[kp0 + 4 * i][lrow] = l0;  BsL[kp0 + 4 * i + 1][lrow] = l1;
        }
        __syncthreads();

        if (k0 + 16 < K) {
#pragma unroll
            for (int i = 0; i < 2; ++i) {
                pa[i] = *(const float4*)(Ag + k0 + 16 + 8 * i);
                pb[i] = *(const float4*)(Bg + k0 + 16 + 8 * i);
            }
        }

        // fragments: a0 = (row r, kpair c), a1 = (r+8, c), a2 = (r, c+4), a3 = (r+8, c+4)
        unsigned aH[4][4], aL[4][4], bH[4][2], bL[4][2];
#pragma unroll
        for (int mt = 0; mt < 4; ++mt) {
            const int mr = wm + mt * 16 + r;
            aH[mt][0] = AsH[c][mr];     aH[mt][1] = AsH[c][mr + 8];
            aH[mt][2] = AsH[c + 4][mr]; aH[mt][3] = AsH[c + 4][mr + 8];
            aL[mt][0] = AsL[c][mr];     aL[mt][1] = AsL[c][mr + 8];
            aL[mt][2] = AsL[c + 4][mr]; aL[mt][3] = AsL[c + 4][mr + 8];
        }
#pragma unroll
        for (int nt = 0; nt < 4; ++nt) {
            const int nr = wn + nt * 8 + r;
            bH[nt][0] = BsH[c][nr]; bH[nt][1] = BsH[c + 4][nr];
            bL[nt][0] = BsL[c][nr]; bL[nt][1] = BsL[c + 4][nr];
        }
#pragma unroll
        for (int mt = 0; mt < 4; ++mt)
#pragma unroll
            for (int nt = 0; nt < 4; ++nt) {
                mma_bf16(acc[mt][nt][0], acc[mt][nt][1], acc[mt][nt][2], acc[mt][nt][3],
                         aH[mt][0], aH[mt][1], aH[mt][2], aH[mt][3],
                         bL[nt][0], bL[nt][1]);
                mma_bf16(acc[mt][nt][0], acc[mt][nt][1], acc[mt][nt][2], acc[mt][nt][3],
                         aL[mt][0], aL[mt][1], aL[mt][2], aL[mt][3],
                         bH[nt][0], bH[nt][1]);
                mma_bf16(acc[mt][nt][0], acc[mt][nt][1], acc[mt][nt][2], acc[mt][nt][3],
                         aH[mt][0], aH[mt][1], aH[mt][2], aH[mt][3],
                         bH[nt][0], bH[nt][1]);
            }
        __syncthreads();
    }

    // Epilogue: d0,d1 @ (r, 2c), d2,d3 @ (r+8, 2c)
#pragma unroll
    for (int mt = 0; mt < 4; ++mt) {
#pragma unroll
        for (int nt = 0; nt < 4; ++nt) {
            const int m = m0 + wm + mt * 16 + r;
            const int n = n0 + wn + nt * 8 + c * 2;
            float2 v0 = make_float2(acc[mt][nt][0], acc[mt][nt][1]);
            float2 v1 = make_float2(acc[mt][nt][2], acc[mt][nt][3]);
            if (HAS_BIAS) {
                const float b0v = bias[n], b1v = bias[n + 1];
                v0.x += b0v; v0.y += b1v;
                v1.x += b0v; v1.y += b1v;
            }
            *(float2*)(C + (size_t)m * N + n)       = v0;
            *(float2*)(C + (size_t)(m + 8) * N + n) = v1;
        }
    }
}

// ---------------------------------------------------------------------------
// Attention logits, split over N (deterministic partials). fp32 FMA.
// ---------------------------------------------------------------------------
__global__ __launch_bounds__(256)
void attn_logits_kernel()
{
    __shared__ float Ks[64][68];
    __shared__ float Qs[64][68];

    const int t = threadIdx.x;
    const int split = blockIdx.x;
    const int bh = blockIdx.y;
    const int b = bh >> 4, h = bh & 15;

    const float* base = g_qkv + (size_t)b * kN * kQKV + h * kD;
    const int td = t >> 4;
    const int te = t & 15;

    float acc[4][4];
#pragma unroll
    for (int i = 0; i < 4; ++i)
#pragma unroll
        for (int j = 0; j < 4; ++j) acc[i][j] = 0.f;

    const int nbeg = split * (kN / kSplits);
    for (int n0 = nbeg; n0 < nbeg + kN / kSplits; n0 += 64) {
#pragma unroll
        for (int i = 0; i < 4; ++i) {
            const int f = t + i * 256;
            const int row = f >> 4;
            const int c4 = (f & 15) * 4;
            const float* p = base + (size_t)(n0 + row) * kQKV + c4;
            *(float4*)&Qs[row][c4] = *(const float4*)(p);
            *(float4*)&Ks[row][c4] = *(const float4*)(p + kC);
        }
        __syncthreads();
#pragma unroll
        for (int nn = 0; nn < 64; ++nn) {
            float a[4], q[4];
            *(float4*)a = *(const float4*)&Ks[nn][td * 4];
            *(float4*)q = *(const float4*)&Qs[nn][te * 4];
#pragma unroll
            for (int i = 0; i < 4; ++i)
#pragma unroll
                for (int j = 0; j < 4; ++j)
                    acc[i][j] = fmaf(a[i], q[j], acc[i][j]);
        }
        __syncthreads();
    }

    float* o = g_attn + ((size_t)split * (kB * kH) + bh) * (kD * kD);
#pragma unroll
    for (int i = 0; i < 4; ++i)
#pragma unroll
        for (int j = 0; j < 4; ++j)
            o[(td * 4 + i) * kD + te * 4 + j] = acc[i][j];
}

// ---------------------------------------------------------------------------
__global__ void softmax_kernel(const float* __restrict__ alpha)
{
    const int row = blockIdx.x;
    const int t = threadIdx.x;
    const int h = (row >> 6) & 15;
    __shared__ float s[64];

    float v = 0.f;
#pragma unroll
    for (int sp = 0; sp < kSplits; ++sp)
        v += g_attn[(size_t)sp * (kB * kH * kD * kD) + (size_t)row * kD + t];
    v /= alpha[h];

    s[t] = v;
    __syncthreads();
    for (int off = 32; off > 0; off >>= 1) {
        if (t < off) s[t] = fmaxf(s[t], s[t + off]);
        __syncthreads();
    }
    const float mx = s[0];
    __syncthreads();
    const float e = expf(v - mx);
    s[t] = e;
    __syncthreads();
    for (int off = 32; off > 0; off >>= 1) {
        if (t < off) s[t] += s[t + off];
        __syncthreads();
    }
    g_attnP[(size_t)row * kD + t] = e / s[0];
}

// ---------------------------------------------------------------------------
__global__ __launch_bounds__(256)
void pv_kernel()
{
    __shared__ float PsT[64][68];
    __shared__ float Vs[64][68];

    const int t = threadIdx.x;
    const int nt = blockIdx.x;
    const int bh = blockIdx.y;
    const int b = bh >> 4, h = bh & 15;

    const float* Pg = g_attnP + (size_t)bh * (kD * kD);
#pragma unroll
    for (int i = 0; i < 4; ++i) {
        const int f = t + i * 256;
        const int dd = f >> 4;
        const int c4 = (f & 15) * 4;
        float4 v = *(const float4*)(Pg + dd * kD + c4);
        PsT[c4 + 0][dd] = v.x; PsT[c4 + 1][dd] = v.y;
        PsT[c4 + 2][dd] = v.z; PsT[c4 + 3][dd] = v.w;
    }
    const float* Vg = g_qkv + ((size_t)b * kN + nt * 64) * kQKV + 2 * kC + h * kD;
#pragma unroll
    for (int i = 0; i < 4; ++i) {
        const int f = t + i * 256;
        const int row = f >> 4;
        const int c4 = (f & 15) * 4;
        *(float4*)&Vs[row][c4] = *(const float4*)(Vg + (size_t)row * kQKV + c4);
    }
    __syncthreads();

    const int tn = t >> 3;
    const int tc = (t & 7) * 8;

    float acc[2][8];
#pragma unroll
    for (int i = 0; i < 2; ++i)
#pragma unroll
        for (int j = 0; j < 8; ++j) acc[i][j] = 0.f;

#pragma unroll
    for (int e = 0; e < 64; ++e) {
        float p[8];
        *(float4*)(p)     = *(const float4*)&PsT[e][tc];
        *(float4*)(p + 4) = *(const float4*)&PsT[e][tc + 4];
#pragma unroll
        for (int i = 0; i < 2; ++i) {
            const float v = Vs[tn * 2 + i][e];
#pragma unroll
            for (int j = 0; j < 8; ++j)
                acc[i][j] = fmaf(v, p[j], acc[i][j]);
        }
    }

#pragma unroll
    for (int i = 0; i < 2; ++i) {
        const size_t n = (size_t)b * kN + nt * 64 + tn * 2 + i;
        float* dst = g_out + n * kC + h * kD + tc;
        *(float4*)(dst)     = make_float4(acc[i][0], acc[i][1], acc[i][2], acc[i][3]);
        *(float4*)(dst + 4) = make_float4(acc[i][4], acc[i][5], acc[i][6], acc[i][7]);
    }
}

// ---------------------------------------------------------------------------
extern "C" void kernel_launch(void* const* d_in, const int* in_sizes, int n_in,
                              void* d_out, int out_size)
{
    const float* x = nullptr;
    const float* Wqkv = nullptr;
    const float* Wproj = nullptr;
    const float* bproj = nullptr;
    const float* alpha = nullptr;
    for (int i = 0; i < n_in; ++i) {
        switch (in_sizes[i]) {
            case kM * kC:    x     = (const float*)d_in[i]; break;
            case kQKV * kC:  Wqkv  = (const float*)d_in[i]; break;
            case kC * kC:    Wproj = (const float*)d_in[i]; break;
            case kC:         bproj = (const float*)d_in[i]; break;
            case kH:         alpha = (const float*)d_in[i]; break;
            default: break;
        }
    }

    float* qkv = nullptr;
    float* outp = nullptr;
    cudaGetSymbolAddress((void**)&qkv, g_qkv);
    cudaGetSymbolAddress((void**)&outp, g_out);

    // 1) QKV projection (bf16x3 tensor cores)
    dim3 g1(kQKV / 128, kM / 128);
    bf16x3_gemm_nt<false><<<g1, 256>>>(x, Wqkv, qkv, nullptr, kM, kQKV, kC);

    // 2) Channel-attention logits
    attn_logits_kernel<<<dim3(kSplits, kB * kH), 256>>>();

    // 3) Softmax
    softmax_kernel<<<kB * kH * kD, kD>>>(alpha);

    // 4) P @ V^T
    pv_kernel<<<dim3(kN / 64, kB * kH), 256>>>();

    // 5) Output projection + bias (bf16x3 tensor cores)
    dim3 g3(kC / 128, kM / 128);
    bf16x3_gemm_nt<true><<<g3, 256>>>(outp, Wproj, (float*)d_out, bproj, kM, kC, kC);
}